// round 5
// baseline (speedup 1.0000x reference)
#include <cuda_runtime.h>
#include <cuda_bf16.h>
#include <cstdint>

#define NB 64
#define CC 32
#define KK 5
#define ADIM 4
#define AHID 256

// ---------------- packed f32x2 helpers ----------------
#define PACK2(out, lo, hi) \
    asm("mov.b64 %0, {%1, %2};" : "=l"(out) : "r"(lo), "r"(hi))
#define FMA2(acc, a, b) \
    asm("fma.rn.f32x2 %0, %1, %2, %0;" : "+l"(acc) : "l"(a), "l"(b))
#define UNPACK2(lo, hi, in) \
    asm("mov.b64 {%0, %1}, %2;" : "=r"(lo), "=r"(hi) : "l"(in))

__device__ __forceinline__ unsigned long long pack_dup(float v) {
    unsigned long long r; unsigned u = __float_as_uint(v);
    PACK2(r, u, u); return r;
}

// ---------------- mma.sync m16n8k16 bf16 (plain sm_103-compatible HMMA) ----------------
#define MMA16816(d, a0, a1, a2, a3, b0, b1) \
    asm volatile("mma.sync.aligned.m16n8k16.row.col.f32.bf16.bf16.f32 " \
        "{%0,%1,%2,%3}, {%4,%5,%6,%7}, {%8,%9}, {%0,%1,%2,%3};" \
        : "+f"((d)[0]), "+f"((d)[1]), "+f"((d)[2]), "+f"((d)[3]) \
        : "r"(a0), "r"(a1), "r"(a2), "r"(a3), "r"(b0), "r"(b1))

__device__ __forceinline__ uint32_t bf16x2_split_hi(float f0, float f1, uint32_t& lo_out) {
    __nv_bfloat16 h0 = __float2bfloat16(f0), h1 = __float2bfloat16(f1);
    float r0 = f0 - __bfloat162float(h0), r1 = f1 - __bfloat162float(h1);
    __nv_bfloat162 hp; hp.x = h0; hp.y = h1;
    __nv_bfloat162 lp; lp.x = __float2bfloat16(r0); lp.y = __float2bfloat16(r1);
    lo_out = *(uint32_t*)&lp;
    return *(uint32_t*)&hp;
}

// ---------------- scratch ----------------
__device__ float g_h1[NB * CC * 128 * 128];
__device__ float g_h2[NB * CC * 64 * 64];
__device__ float g_ker[NB * CC * KK * KK];
__device__ float g_sa[NB * CC * 64 * 64];
__device__ float g_f [NB * CC * 64 * 64];
// pre-split weights, u32 bf16x2 [tap][{hi,lo}][oc*16+icpair]: conv2 at 0 (25 taps), mp1 at 25*1024 (9 taps)
__device__ uint32_t g_wtu[34 * 1024];

// =================== action encoder MLP ===================
__global__ void ae_kernel(const float* __restrict__ act,
                          const float* __restrict__ w1, const float* __restrict__ b1,
                          const float* __restrict__ w2, const float* __restrict__ b2) {
    __shared__ float sH[AHID];
    __shared__ float sA[ADIM];
    int n = blockIdx.x, tid = threadIdx.x;
    if (tid < ADIM) sA[tid] = act[n * ADIM + tid];
    __syncthreads();
    float h = b1[tid];
#pragma unroll
    for (int i = 0; i < ADIM; i++) h = fmaf(sA[i], w1[i * AHID + tid], h);
    sH[tid] = fmaxf(h, 0.f);
    __syncthreads();
    for (int o = tid; o < CC * KK * KK; o += 256) {
        float acc = b2[o];
#pragma unroll 8
        for (int j = 0; j < AHID; j++) acc = fmaf(sH[j], w2[j * (CC * KK * KK) + o], acc);
        g_ker[n * (CC * KK * KK) + o] = acc;
    }
}

// =================== weight pre-split (bf16 hi/lo, [oc][icpair] pairs) ===================
__global__ void wsplit_kernel(const float* __restrict__ w, int taps, int dst_off) {
    int i = blockIdx.x * 256 + threadIdx.x;
    if (i >= taps * 512) return;
    int tap = i >> 9, rr = i & 511, oc = rr >> 4, p = rr & 15;
    float f0 = w[(oc * 32 + 2 * p) * taps + tap];
    float f1 = w[(oc * 32 + 2 * p + 1) * taps + tap];
    uint32_t lo, hi = bf16x2_split_hi(f0, f1, lo);
    g_wtu[dst_off + tap * 1024 + oc * 16 + p] = hi;
    g_wtu[dst_off + tap * 1024 + 512 + oc * 16 + p] = lo;
}

// =================== tap-GEMM conv via mma.sync (32ic -> 32oc) ===================
// Block: 256 threads = 8 warps, computes 2 output rows (128 pixels) x 32 oc for one sample.
// Per tap t=(kh,kw): D[128,32] += A[128,32ic] * W_t[32ic,32oc], bf16 2-term split (3 MMA terms).
// smem: [0..2560) W double-buffer (2 bufs x {hi,lo} x 32oc x 20-padded icpairs)
//       [2560..)  halo HI planes (PLANE*16 u32), then halo LO planes.
template<int KS, int STRIDE, int HALO_H, int HALO_W>
__global__ void __launch_bounds__(256)
tapgemm_kernel(const float* __restrict__ in, int IH, int IW,
               const uint32_t* __restrict__ wsp,
               const float* __restrict__ bias,
               float* __restrict__ outp) {
    extern __shared__ uint32_t sm[];
    constexpr int TAPS = KS * KS;
    constexpr int PLANE = HALO_H * HALO_W;
    constexpr int PAD = KS / 2;
    uint32_t* sW = sm;                 // 2 * 1280 u32
    uint32_t* sHI = sm + 2560;
    uint32_t* sLO = sHI + PLANE * 16;

    int tid = threadIdx.x;
    int ytile = blockIdx.x, n = blockIdx.y;
    const float* inb = in + (size_t)n * 32 * IH * IW;
    int gy0 = 2 * STRIDE * ytile - PAD;

    // ---- halo load + bf16 hi/lo split into ic-pair planes ----
    for (int i = tid; i < PLANE * 16; i += 256) {
        int p = i / PLANE, r = i % PLANE, y = r / HALO_W, x = r % HALO_W;
        int gy = gy0 + y, gx = x - PAD;
        float f0 = 0.f, f1 = 0.f;
        if ((unsigned)gy < (unsigned)IH && (unsigned)gx < (unsigned)IW) {
            const float* bp = inb + (size_t)(2 * p) * IH * IW + gy * IW + gx;
            f0 = bp[0]; f1 = bp[IH * IW];
        }
        uint32_t lo, hi = bf16x2_split_hi(f0, f1, lo);
        sHI[i] = hi; sLO[i] = lo;
    }
    // prologue: weights for tap 0 into buf 0 (padded stride 20)
    for (int j = tid; j < 1024; j += 256) {
        int sel = j >> 9, rr = j & 511, oc = rr >> 4, p = rr & 15;
        sW[sel * 640 + oc * 20 + p] = wsp[j];
    }
    __syncthreads();

    int lane = tid & 31, w = tid >> 5;
    int r = lane >> 2, q = lane & 3;
    int px = w * 16 + r;               // pixel for a0/a2 rows (a1/a3: px+8)
    int oyr = px >> 6, ox = px & 63;

    float acc[4][4];
#pragma unroll
    for (int nt = 0; nt < 4; nt++)
#pragma unroll
        for (int e = 0; e < 4; e++) acc[nt][e] = 0.f;

    for (int t = 0; t < TAPS; t++) {
        int buf = t & 1;
        if (t + 1 < TAPS) {
            const uint32_t* src = wsp + (t + 1) * 1024;
            for (int j = tid; j < 1024; j += 256) {
                int sel = j >> 9, rr = j & 511, oc = rr >> 4, p = rr & 15;
                sW[(1 - buf) * 1280 + sel * 640 + oc * 20 + p] = src[j];
            }
        }
        int kh = t / KS, kw = t % KS;
        int base = (STRIDE * oyr + kh) * HALO_W + STRIDE * ox + kw;
        const uint32_t* bh = &sW[buf * 1280];
        const uint32_t* bl = bh + 640;
#pragma unroll
        for (int ks = 0; ks < 2; ks++) {
            int p0 = q + 8 * ks, p2 = q + 4 + 8 * ks;
            uint32_t ah0 = sHI[p0 * PLANE + base];
            uint32_t ah1 = sHI[p0 * PLANE + base + 8 * STRIDE];
            uint32_t ah2 = sHI[p2 * PLANE + base];
            uint32_t ah3 = sHI[p2 * PLANE + base + 8 * STRIDE];
            uint32_t al0 = sLO[p0 * PLANE + base];
            uint32_t al1 = sLO[p0 * PLANE + base + 8 * STRIDE];
            uint32_t al2 = sLO[p2 * PLANE + base];
            uint32_t al3 = sLO[p2 * PLANE + base + 8 * STRIDE];
            uint32_t bhr[4][2], blr[4][2];
#pragma unroll
            for (int nt = 0; nt < 4; nt++) {
                int oc = nt * 8 + r;
                bhr[nt][0] = bh[oc * 20 + p0];
                bhr[nt][1] = bh[oc * 20 + p2];
                blr[nt][0] = bl[oc * 20 + p0];
                blr[nt][1] = bl[oc * 20 + p2];
            }
#pragma unroll
            for (int nt = 0; nt < 4; nt++)
                MMA16816(acc[nt], ah0, ah1, ah2, ah3, bhr[nt][0], bhr[nt][1]);
#pragma unroll
            for (int nt = 0; nt < 4; nt++)
                MMA16816(acc[nt], al0, al1, al2, al3, bhr[nt][0], bhr[nt][1]);
#pragma unroll
            for (int nt = 0; nt < 4; nt++)
                MMA16816(acc[nt], ah0, ah1, ah2, ah3, blr[nt][0], blr[nt][1]);
        }
        __syncthreads();
    }

    // ---- epilogue: stage D through smem (reuse halo region), coalesced store ----
    float* sD = (float*)sHI;           // 32 oc x 128 px = 16 KB (fits both instantiations)
#pragma unroll
    for (int nt = 0; nt < 4; nt++) {
        int oc = nt * 8 + 2 * q;
        sD[oc * 128 + px] = acc[nt][0];
        sD[(oc + 1) * 128 + px] = acc[nt][1];
        sD[oc * 128 + px + 8] = acc[nt][2];
        sD[(oc + 1) * 128 + px + 8] = acc[nt][3];
    }
    __syncthreads();
    float* outb = outp + (size_t)n * 32 * 4096;
    for (int j = tid; j < 4096; j += 256) {
        int oc = j >> 7, m = j & 127;
        int gy = 2 * ytile + (m >> 6), gx = m & 63;
        float v = sD[j] + __ldg(&bias[oc]);
        outb[oc * 4096 + gy * 64 + gx] = fmaxf(v, 0.f);
    }
}

// =================== conv1: 3->32, k5, s2, p2, NHWC in (scalar FFMA2) ===================
__global__ void __launch_bounds__(256, 2)
conv1_kernel(const float* __restrict__ img,
             const float* __restrict__ w, const float* __restrict__ b) {
    __shared__ __align__(8) float sIn[3 * 35 * 67];
    __shared__ __align__(8) float sW[75 * 32];
    __shared__ __align__(8) float sB[32];
    int n = blockIdx.z;
    int ox0 = blockIdx.x * 32, oy0 = blockIdx.y * 16;
    int tid = threadIdx.x;

    for (int i = tid; i < 75 * 32; i += 256) {
        int o = i & 31, tap = i >> 5;
        int c = tap / 25, r = tap % 25, kh = r / 5, kw = r % 5;
        sW[i] = w[((o * 3 + c) * 5 + kh) * 5 + kw];
    }
    if (tid < 32) sB[tid] = b[tid];

    int iy0 = oy0 * 2 - 2, ix0 = ox0 * 2 - 2;
    for (int i = tid; i < 3 * 35 * 67; i += 256) {
        int c = i / (35 * 67), r = i % (35 * 67);
        int iy = r / 67, ix = r % 67;
        int gy = iy0 + iy, gx = ix0 + ix;
        float v = 0.f;
        if ((unsigned)gy < 256u && (unsigned)gx < 256u)
            v = img[((n * 256 + gy) * 256 + gx) * 3 + c];
        sIn[i] = v;
    }
    __syncthreads();

    int ox = tid & 31, oyr = tid >> 5;
    unsigned long long accA[16], accB[16];
    const unsigned long long* sB2 = (const unsigned long long*)sB;
#pragma unroll
    for (int o = 0; o < 16; o++) { accA[o] = sB2[o]; accB[o] = sB2[o]; }

    for (int c = 0; c < 3; c++)
        for (int kh = 0; kh < 5; kh++) {
            const float* rA = &sIn[c * (35 * 67) + (oyr * 2 + kh) * 67 + ox * 2];
            const float* rB = rA + 16 * 67;
#pragma unroll
            for (int kw = 0; kw < 5; kw++) {
                unsigned long long vA2 = pack_dup(rA[kw]);
                unsigned long long vB2 = pack_dup(rB[kw]);
                const unsigned long long* wp =
                    (const unsigned long long*)&sW[((c * 5 + kh) * 5 + kw) * 32];
#pragma unroll
                for (int o = 0; o < 16; o++) {
                    unsigned long long w2 = wp[o];
                    FMA2(accA[o], vA2, w2);
                    FMA2(accB[o], vB2, w2);
                }
            }
        }

    int gyA = oy0 + oyr, gyB = gyA + 8, gx = ox0 + ox;
#pragma unroll
    for (int o = 0; o < 16; o++) {
        unsigned lo, hi;
        UNPACK2(lo, hi, accA[o]);
        g_h1[((n * 32 + 2 * o) * 128 + gyA) * 128 + gx] = fmaxf(__uint_as_float(lo), 0.f);
        g_h1[((n * 32 + 2 * o + 1) * 128 + gyA) * 128 + gx] = fmaxf(__uint_as_float(hi), 0.f);
        UNPACK2(lo, hi, accB[o]);
        g_h1[((n * 32 + 2 * o) * 128 + gyB) * 128 + gx] = fmaxf(__uint_as_float(lo), 0.f);
        g_h1[((n * 32 + 2 * o + 1) * 128 + gyB) * 128 + gx] = fmaxf(__uint_as_float(hi), 0.f);
    }
}

// =================== cross-conv: per-sample depthwise k5 p2 ===================
__global__ void xconv_kernel() {
    __shared__ float sIn[68 * 68];
    __shared__ float sK[25];
    int c = blockIdx.x, n = blockIdx.y;
    int tid = threadIdx.x;
    const float* src = &g_h2[(n * 32 + c) * 4096];
    for (int i = tid; i < 68 * 68; i += 256) {
        int iy = i / 68, ix = i % 68;
        int gy = iy - 2, gx = ix - 2;
        sIn[i] = ((unsigned)gy < 64u && (unsigned)gx < 64u) ? src[gy * 64 + gx] : 0.f;
    }
    if (tid < 25) sK[tid] = g_ker[(n * 32 + c) * 25 + tid];
    __syncthreads();
    float k[25];
#pragma unroll
    for (int t = 0; t < 25; t++) k[t] = sK[t];
    for (int p = tid; p < 4096; p += 256) {
        int y = p >> 6, x = p & 63;
        float acc = 0.f;
#pragma unroll
        for (int kh = 0; kh < 5; kh++)
#pragma unroll
            for (int kw = 0; kw < 5; kw++)
                acc = fmaf(sIn[(y + kh) * 68 + (x + kw)], k[kh * 5 + kw], acc);
        g_sa[(n * 32 + c) * 4096 + p] = acc;
    }
}

// =================== mp2: 32->2, k3, p1 ===================
__global__ void __launch_bounds__(256, 2)
mp2_kernel(const float* __restrict__ w, const float* __restrict__ b,
           float* __restrict__ out) {
    __shared__ __align__(8) float sIn[2][10 * 34];
    __shared__ __align__(8) float sW[2][18];
    int n = blockIdx.z;
    int ox0 = blockIdx.x * 32, oy0 = blockIdx.y * 8;
    int tid = threadIdx.x;
    int ox = tid & 31, oy = tid >> 5;

    int iy0 = oy0 - 1, ix0 = ox0 - 1;

    float pin[2], pwv;
    {
        const float* src = &g_f[(n * 32 + 0) * 4096];
#pragma unroll
        for (int j = 0; j < 2; j++) {
            int i = tid + j * 256; float v = 0.f;
            if (i < 340) {
                int iy = i / 34, ix = i % 34;
                int gy = iy0 + iy, gx = ix0 + ix;
                if ((unsigned)gy < 64u && (unsigned)gx < 64u) v = src[gy * 64 + gx];
            }
            pin[j] = v;
        }
        pwv = (tid < 18) ? w[((tid & 1) * 32 + 0) * 9 + (tid >> 1)] : 0.f;
    }
#pragma unroll
    for (int j = 0; j < 2; j++) { int i = tid + j * 256; if (i < 340) sIn[0][i] = pin[j]; }
    if (tid < 18) sW[0][tid] = pwv;
    __syncthreads();

    unsigned long long acc2;
    PACK2(acc2, __float_as_uint(b[0]), __float_as_uint(b[1]));

    for (int ic = 0; ic < 32; ic++) {
        int cur = ic & 1;
        if (ic < 31) {
            const float* src = &g_f[(n * 32 + ic + 1) * 4096];
#pragma unroll
            for (int j = 0; j < 2; j++) {
                int i = tid + j * 256; float v = 0.f;
                if (i < 340) {
                    int iy = i / 34, ix = i % 34;
                    int gy = iy0 + iy, gx = ix0 + ix;
                    if ((unsigned)gy < 64u && (unsigned)gx < 64u) v = src[gy * 64 + gx];
                }
                pin[j] = v;
            }
            pwv = (tid < 18) ? w[((tid & 1) * 32 + ic + 1) * 9 + (tid >> 1)] : 0.f;
        }
        const unsigned long long* wp2 = (const unsigned long long*)&sW[cur][0];
#pragma unroll
        for (int kh = 0; kh < 3; kh++) {
            const float* row = &sIn[cur][(oy + kh) * 34 + ox];
#pragma unroll
            for (int kw = 0; kw < 3; kw++) {
                unsigned long long v2 = pack_dup(row[kw]);
                FMA2(acc2, v2, wp2[kh * 3 + kw]);
            }
        }
        if (ic < 31) {
#pragma unroll
            for (int j = 0; j < 2; j++) { int i = tid + j * 256; if (i < 340) sIn[1 - cur][i] = pin[j]; }
            if (tid < 18) sW[1 - cur][tid] = pwv;
        }
        __syncthreads();
    }
    int gy = oy0 + oy, gx = ox0 + ox;
    unsigned lo, hi;
    UNPACK2(lo, hi, acc2);
    out[((n * 2 + 0) * 64 + gy) * 64 + gx] = __uint_as_float(lo);
    out[((n * 2 + 1) * 64 + gy) * 64 + gx] = __uint_as_float(hi);
}

// =================== launch ===================
#define C2_SMEM ((2560 + 2 * 7 * 132 * 16) * 4)   // 128512 B
#define MP1_SMEM ((2560 + 2 * 4 * 66 * 16) * 4)   // 44032 B

extern "C" void kernel_launch(void* const* d_in, const int* in_sizes, int n_in,
                              void* d_out, int out_size) {
    const float* images = (const float*)d_in[0];
    const float* actions = (const float*)d_in[1];
    const float* pe_w1 = (const float*)d_in[2];
    const float* pe_b1 = (const float*)d_in[3];
    const float* pe_w2 = (const float*)d_in[4];
    const float* pe_b2 = (const float*)d_in[5];
    const float* ae_w1 = (const float*)d_in[6];
    const float* ae_b1 = (const float*)d_in[7];
    const float* ae_w2 = (const float*)d_in[8];
    const float* ae_b2 = (const float*)d_in[9];
    const float* mp_w1 = (const float*)d_in[10];
    const float* mp_b1 = (const float*)d_in[11];
    const float* mp_w2 = (const float*)d_in[12];
    const float* mp_b2 = (const float*)d_in[13];
    float* out = (float*)d_out;

    cudaFuncSetAttribute((const void*)tapgemm_kernel<5, 2, 7, 132>,
                         cudaFuncAttributeMaxDynamicSharedMemorySize, C2_SMEM);
    cudaFuncSetAttribute((const void*)tapgemm_kernel<3, 1, 4, 66>,
                         cudaFuncAttributeMaxDynamicSharedMemorySize, MP1_SMEM);

    // device pointers to the weight scratch (module-scope symbol address is constant)
    uint32_t* wtu;
    cudaGetSymbolAddress((void**)&wtu, g_wtu);
    float* h1p; cudaGetSymbolAddress((void**)&h1p, g_h1);
    float* h2p; cudaGetSymbolAddress((void**)&h2p, g_h2);
    float* sap; cudaGetSymbolAddress((void**)&sap, g_sa);
    float* fp;  cudaGetSymbolAddress((void**)&fp, g_f);

    ae_kernel<<<NB, 256>>>(actions, ae_w1, ae_b1, ae_w2, ae_b2);
    wsplit_kernel<<<50, 256>>>(pe_w2, 25, 0);
    wsplit_kernel<<<18, 256>>>(mp_w1, 9, 25 * 1024);
    conv1_kernel<<<dim3(4, 8, NB), 256>>>(images, pe_w1, pe_b1);
    tapgemm_kernel<5, 2, 7, 132><<<dim3(32, NB), 256, C2_SMEM>>>(
        h1p, 128, 128, wtu, pe_b2, h2p);
    xconv_kernel<<<dim3(32, NB), 256>>>();
    tapgemm_kernel<3, 1, 4, 66><<<dim3(32, NB), 256, MP1_SMEM>>>(
        sap, 64, 64, wtu + 25 * 1024, mp_b1, fp);
    mp2_kernel<<<dim3(2, 8, NB), 256>>>(mp_w2, mp_b2, out);
}

// round 6
// speedup vs baseline: 1.5227x; 1.5227x over previous
#include <cuda_runtime.h>
#include <cuda_bf16.h>
#include <cstdint>

#define NB 64
#define CC 32
#define KK 5
#define ADIM 4
#define AHID 256

// packed f32x2 helpers (sm_100+): one instruction = 2 fp32 FMAs per lane
#define PACK2(out, lo, hi) \
    asm("mov.b64 %0, {%1, %2};" : "=l"(out) : "r"(lo), "r"(hi))
#define FMA2(acc, a, b) \
    asm("fma.rn.f32x2 %0, %1, %2, %0;" : "+l"(acc) : "l"(a), "l"(b))
#define UNPACK2(lo, hi, in) \
    asm("mov.b64 {%0, %1}, %2;" : "=r"(lo), "=r"(hi) : "l"(in))

__device__ __forceinline__ unsigned long long pack_dup(float v) {
    unsigned long long r; unsigned u = __float_as_uint(v);
    PACK2(r, u, u); return r;
}

// ---------------- scratch ----------------
__device__ float g_h1[NB * CC * 128 * 128];
__device__ float g_h2[NB * CC * 64 * 64];
__device__ float g_ker[NB * CC * KK * KK];
__device__ float g_sa[NB * CC * 64 * 64];
__device__ float g_f [NB * CC * 64 * 64];

// =================== action encoder MLP ===================
__global__ void ae_kernel(const float* __restrict__ act,
                          const float* __restrict__ w1, const float* __restrict__ b1,
                          const float* __restrict__ w2, const float* __restrict__ b2) {
    __shared__ float sH[AHID];
    __shared__ float sA[ADIM];
    int n = blockIdx.x, tid = threadIdx.x;
    if (tid < ADIM) sA[tid] = act[n * ADIM + tid];
    __syncthreads();
    float h = b1[tid];
#pragma unroll
    for (int i = 0; i < ADIM; i++) h = fmaf(sA[i], w1[i * AHID + tid], h);
    sH[tid] = fmaxf(h, 0.f);
    __syncthreads();
    for (int o = tid; o < CC * KK * KK; o += 256) {
        float acc = b2[o];
#pragma unroll 8
        for (int j = 0; j < AHID; j++) acc = fmaf(sH[j], w2[j * (CC * KK * KK) + o], acc);
        g_ker[n * (CC * KK * KK) + o] = acc;
    }
}

// =================== conv1: 3->32, k5, s2, p2, NHWC in ===================
// parity-split input planes (conflict-free LDS), LDS.128 weight reads
__global__ void __launch_bounds__(256, 2)
conv1_kernel(const float* __restrict__ img,
             const float* __restrict__ w, const float* __restrict__ b) {
    __shared__ __align__(16) float sIn[2][3 * 35 * 34];   // [parity][c][row][x/2]
    __shared__ __align__(16) float sW[75 * 32];
    __shared__ __align__(8) float sB[32];
    int n = blockIdx.z;
    int ox0 = blockIdx.x * 32, oy0 = blockIdx.y * 16;
    int tid = threadIdx.x;

    for (int i = tid; i < 75 * 32; i += 256) {
        int o = i & 31, tap = i >> 5;
        int c = tap / 25, r = tap % 25, kh = r / 5, kw = r % 5;
        sW[i] = w[((o * 3 + c) * 5 + kh) * 5 + kw];
    }
    if (tid < 32) sB[tid] = b[tid];

    int iy0 = oy0 * 2 - 2, ix0 = ox0 * 2 - 2;
    for (int i = tid; i < 3 * 35 * 67; i += 256) {
        int c = i / (35 * 67), r = i % (35 * 67);
        int iy = r / 67, ix = r % 67;
        int gy = iy0 + iy, gx = ix0 + ix;
        float v = 0.f;
        if ((unsigned)gy < 256u && (unsigned)gx < 256u)
            v = img[((n * 256 + gy) * 256 + gx) * 3 + c];
        sIn[ix & 1][c * 1190 + iy * 34 + (ix >> 1)] = v;
    }
    __syncthreads();

    int ox = tid & 31, oyr = tid >> 5;
    unsigned long long accA[16], accB[16];
    const unsigned long long* sB2 = (const unsigned long long*)sB;
#pragma unroll
    for (int o = 0; o < 16; o++) { accA[o] = sB2[o]; accB[o] = sB2[o]; }

    for (int c = 0; c < 3; c++)
        for (int kh = 0; kh < 5; kh++) {
            int base = c * 1190 + (2 * oyr + kh) * 34 + ox;
            const float* pl[2] = { &sIn[0][base], &sIn[1][base] };
#pragma unroll
            for (int kw = 0; kw < 5; kw++) {
                float fA = pl[kw & 1][kw >> 1];
                float fB = pl[kw & 1][(kw >> 1) + 544];
                unsigned long long vA2 = pack_dup(fA);
                unsigned long long vB2 = pack_dup(fB);
                const ulonglong2* wq =
                    (const ulonglong2*)&sW[((c * 5 + kh) * 5 + kw) * 32];
#pragma unroll
                for (int o2 = 0; o2 < 8; o2++) {
                    ulonglong2 ww = wq[o2];
                    FMA2(accA[2 * o2], vA2, ww.x);
                    FMA2(accA[2 * o2 + 1], vA2, ww.y);
                    FMA2(accB[2 * o2], vB2, ww.x);
                    FMA2(accB[2 * o2 + 1], vB2, ww.y);
                }
            }
        }

    int gyA = oy0 + oyr, gyB = gyA + 8, gx = ox0 + ox;
#pragma unroll
    for (int o = 0; o < 16; o++) {
        unsigned lo, hi;
        UNPACK2(lo, hi, accA[o]);
        g_h1[((n * 32 + 2 * o) * 128 + gyA) * 128 + gx] = fmaxf(__uint_as_float(lo), 0.f);
        g_h1[((n * 32 + 2 * o + 1) * 128 + gyA) * 128 + gx] = fmaxf(__uint_as_float(hi), 0.f);
        UNPACK2(lo, hi, accB[o]);
        g_h1[((n * 32 + 2 * o) * 128 + gyB) * 128 + gx] = fmaxf(__uint_as_float(lo), 0.f);
        g_h1[((n * 32 + 2 * o + 1) * 128 + gyB) * 128 + gx] = fmaxf(__uint_as_float(hi), 0.f);
    }
}

// =================== conv2: 32->32, k5, s2, p2 ===================
// parity-split double-buffered halo, LDS.128 weights, reg prefetch, 1 sync/ic
__global__ void __launch_bounds__(256, 2)
conv2_kernel(const float* __restrict__ w, const float* __restrict__ b) {
    __shared__ __align__(16) float sIn[2][2][1190];   // [buf][parity][35 x 34]
    __shared__ __align__(16) float sW[2][800];
    __shared__ __align__(8) float sB[32];
    int n = blockIdx.z;
    int ox0 = blockIdx.x * 32, oy0 = blockIdx.y * 16;
    int tid = threadIdx.x;
    int ox = tid & 31, oyr = tid >> 5;
    if (tid < 32) sB[tid] = b[tid];

    int iy0 = oy0 * 2 - 2, ix0 = ox0 * 2 - 2;

    float pin[10], pw[4];
    {
        const float* src = &g_h1[(n * 32 + 0) * 16384];
#pragma unroll
        for (int j = 0; j < 10; j++) {
            int i = tid + j * 256; float v = 0.f;
            if (i < 2345) {
                int iy = i / 67, ix = i % 67;
                int gy = iy0 + iy, gx = ix0 + ix;
                if ((unsigned)gy < 128u && (unsigned)gx < 128u) v = src[gy * 128 + gx];
            }
            pin[j] = v;
        }
#pragma unroll
        for (int j = 0; j < 4; j++) {
            int i = tid + j * 256; float v = 0.f;
            if (i < 800) { int o = i & 31, tap = i >> 5; v = w[(o * 32 + 0) * 25 + tap]; }
            pw[j] = v;
        }
    }
#pragma unroll
    for (int j = 0; j < 10; j++) {
        int i = tid + j * 256;
        if (i < 2345) {
            int iy = i / 67, ix = i % 67;
            sIn[0][ix & 1][iy * 34 + (ix >> 1)] = pin[j];
        }
    }
#pragma unroll
    for (int j = 0; j < 4; j++) { int i = tid + j * 256; if (i < 800) sW[0][i] = pw[j]; }
    __syncthreads();

    unsigned long long accA[16], accB[16];
    const unsigned long long* sB2 = (const unsigned long long*)sB;
#pragma unroll
    for (int o = 0; o < 16; o++) { accA[o] = sB2[o]; accB[o] = sB2[o]; }

    for (int ic = 0; ic < 32; ic++) {
        int cur = ic & 1;
        if (ic < 31) {
            const float* src = &g_h1[(n * 32 + ic + 1) * 16384];
#pragma unroll
            for (int j = 0; j < 10; j++) {
                int i = tid + j * 256; float v = 0.f;
                if (i < 2345) {
                    int iy = i / 67, ix = i % 67;
                    int gy = iy0 + iy, gx = ix0 + ix;
                    if ((unsigned)gy < 128u && (unsigned)gx < 128u) v = src[gy * 128 + gx];
                }
                pin[j] = v;
            }
#pragma unroll
            for (int j = 0; j < 4; j++) {
                int i = tid + j * 256; float v = 0.f;
                if (i < 800) { int o = i & 31, tap = i >> 5; v = w[(o * 32 + ic + 1) * 25 + tap]; }
                pw[j] = v;
            }
        }
#pragma unroll
        for (int kh = 0; kh < 5; kh++) {
            int base = (2 * oyr + kh) * 34 + ox;
            const float* pl[2] = { &sIn[cur][0][base], &sIn[cur][1][base] };
#pragma unroll
            for (int kw = 0; kw < 5; kw++) {
                float fA = pl[kw & 1][kw >> 1];
                float fB = pl[kw & 1][(kw >> 1) + 544];
                unsigned long long vA2 = pack_dup(fA);
                unsigned long long vB2 = pack_dup(fB);
                const ulonglong2* wq = (const ulonglong2*)&sW[cur][(kh * 5 + kw) * 32];
#pragma unroll
                for (int o2 = 0; o2 < 8; o2++) {
                    ulonglong2 ww = wq[o2];
                    FMA2(accA[2 * o2], vA2, ww.x);
                    FMA2(accA[2 * o2 + 1], vA2, ww.y);
                    FMA2(accB[2 * o2], vB2, ww.x);
                    FMA2(accB[2 * o2 + 1], vB2, ww.y);
                }
            }
        }
        if (ic < 31) {
#pragma unroll
            for (int j = 0; j < 10; j++) {
                int i = tid + j * 256;
                if (i < 2345) {
                    int iy = i / 67, ix = i % 67;
                    sIn[1 - cur][ix & 1][iy * 34 + (ix >> 1)] = pin[j];
                }
            }
#pragma unroll
            for (int j = 0; j < 4; j++) { int i = tid + j * 256; if (i < 800) sW[1 - cur][i] = pw[j]; }
        }
        __syncthreads();
    }

    int gyA = oy0 + oyr, gyB = gyA + 8, gx = ox0 + ox;
#pragma unroll
    for (int o = 0; o < 16; o++) {
        unsigned lo, hi;
        UNPACK2(lo, hi, accA[o]);
        g_h2[((n * 32 + 2 * o) * 64 + gyA) * 64 + gx] = fmaxf(__uint_as_float(lo), 0.f);
        g_h2[((n * 32 + 2 * o + 1) * 64 + gyA) * 64 + gx] = fmaxf(__uint_as_float(hi), 0.f);
        UNPACK2(lo, hi, accB[o]);
        g_h2[((n * 32 + 2 * o) * 64 + gyB) * 64 + gx] = fmaxf(__uint_as_float(lo), 0.f);
        g_h2[((n * 32 + 2 * o + 1) * 64 + gyB) * 64 + gx] = fmaxf(__uint_as_float(hi), 0.f);
    }
}

// =================== cross-conv: depthwise k5 p2, register row-reuse ===================
// 64x4 thread layout; each thread computes a 16-tall column. Each loaded input
// row value feeds up to 5 kh taps -> LDS count cut ~4x vs 1-px version.
__global__ void __launch_bounds__(256)
xconv_kernel() {
    __shared__ float sIn[68 * 68];
    __shared__ float sK[25];
    int c = blockIdx.x, n = blockIdx.y;
    int tid = threadIdx.x;
    const float* src = &g_h2[(n * 32 + c) * 4096];
    for (int i = tid; i < 68 * 68; i += 256) {
        int iy = i / 68, ix = i % 68;
        int gy = iy - 2, gx = ix - 2;
        sIn[i] = ((unsigned)gy < 64u && (unsigned)gx < 64u) ? src[gy * 64 + gx] : 0.f;
    }
    if (tid < 25) sK[tid] = g_ker[(n * 32 + c) * 25 + tid];
    __syncthreads();
    float k[25];
#pragma unroll
    for (int t = 0; t < 25; t++) k[t] = sK[t];

    int tx = tid & 63, ty = tid >> 6;
    int ybase = ty * 16;
    float acc[16];
#pragma unroll
    for (int j = 0; j < 16; j++) acc[j] = 0.f;

#pragma unroll
    for (int iy = 0; iy < 20; iy++) {
        const float* row = &sIn[(ybase + iy) * 68 + tx];
        float v0 = row[0], v1 = row[1], v2 = row[2], v3 = row[3], v4 = row[4];
#pragma unroll
        for (int kh = 0; kh < 5; kh++) {
            int j = iy - kh;
            if (j >= 0 && j < 16) {
                float a = acc[j];
                a = fmaf(v0, k[kh * 5 + 0], a);
                a = fmaf(v1, k[kh * 5 + 1], a);
                a = fmaf(v2, k[kh * 5 + 2], a);
                a = fmaf(v3, k[kh * 5 + 3], a);
                a = fmaf(v4, k[kh * 5 + 4], a);
                acc[j] = a;
            }
        }
    }
    float* dst = &g_sa[(n * 32 + c) * 4096 + tx];
#pragma unroll
    for (int j = 0; j < 16; j++) dst[(ybase + j) * 64] = acc[j];
}

// =================== mp1: 32->32, k3, p1, relu ===================
__global__ void __launch_bounds__(256, 2)
mp1_kernel(const float* __restrict__ w, const float* __restrict__ b) {
    __shared__ __align__(16) float sIn[2][18 * 34];
    __shared__ __align__(16) float sW[2][288];
    __shared__ __align__(8) float sB[32];
    int n = blockIdx.z;
    int ox0 = blockIdx.x * 32, oy0 = blockIdx.y * 16;
    int tid = threadIdx.x;
    int ox = tid & 31, oyr = tid >> 5;
    if (tid < 32) sB[tid] = b[tid];

    int iy0 = oy0 - 1, ix0 = ox0 - 1;

    float pin[3], pw[2];
    {
        const float* src = &g_sa[(n * 32 + 0) * 4096];
#pragma unroll
        for (int j = 0; j < 3; j++) {
            int i = tid + j * 256; float v = 0.f;
            if (i < 612) {
                int iy = i / 34, ix = i % 34;
                int gy = iy0 + iy, gx = ix0 + ix;
                if ((unsigned)gy < 64u && (unsigned)gx < 64u) v = src[gy * 64 + gx];
            }
            pin[j] = v;
        }
#pragma unroll
        for (int j = 0; j < 2; j++) {
            int i = tid + j * 256; float v = 0.f;
            if (i < 288) { int o = i & 31, tap = i >> 5; v = w[(o * 32 + 0) * 9 + tap]; }
            pw[j] = v;
        }
    }
#pragma unroll
    for (int j = 0; j < 3; j++) { int i = tid + j * 256; if (i < 612) sIn[0][i] = pin[j]; }
#pragma unroll
    for (int j = 0; j < 2; j++) { int i = tid + j * 256; if (i < 288) sW[0][i] = pw[j]; }
    __syncthreads();

    unsigned long long accA[16], accB[16];
    const unsigned long long* sB2 = (const unsigned long long*)sB;
#pragma unroll
    for (int o = 0; o < 16; o++) { accA[o] = sB2[o]; accB[o] = sB2[o]; }

    for (int ic = 0; ic < 32; ic++) {
        int cur = ic & 1;
        if (ic < 31) {
            const float* src = &g_sa[(n * 32 + ic + 1) * 4096];
#pragma unroll
            for (int j = 0; j < 3; j++) {
                int i = tid + j * 256; float v = 0.f;
                if (i < 612) {
                    int iy = i / 34, ix = i % 34;
                    int gy = iy0 + iy, gx = ix0 + ix;
                    if ((unsigned)gy < 64u && (unsigned)gx < 64u) v = src[gy * 64 + gx];
                }
                pin[j] = v;
            }
#pragma unroll
            for (int j = 0; j < 2; j++) {
                int i = tid + j * 256; float v = 0.f;
                if (i < 288) { int o = i & 31, tap = i >> 5; v = w[(o * 32 + ic + 1) * 9 + tap]; }
                pw[j] = v;
            }
        }
#pragma unroll
        for (int kh = 0; kh < 3; kh++) {
            const float* rA = &sIn[cur][(oyr + kh) * 34 + ox];
            const float* rB = rA + 8 * 34;
#pragma unroll
            for (int kw = 0; kw < 3; kw++) {
                unsigned long long vA2 = pack_dup(rA[kw]);
                unsigned long long vB2 = pack_dup(rB[kw]);
                const ulonglong2* wq = (const ulonglong2*)&sW[cur][(kh * 3 + kw) * 32];
#pragma unroll
                for (int o2 = 0; o2 < 8; o2++) {
                    ulonglong2 ww = wq[o2];
                    FMA2(accA[2 * o2], vA2, ww.x);
                    FMA2(accA[2 * o2 + 1], vA2, ww.y);
                    FMA2(accB[2 * o2], vB2, ww.x);
                    FMA2(accB[2 * o2 + 1], vB2, ww.y);
                }
            }
        }
        if (ic < 31) {
#pragma unroll
            for (int j = 0; j < 3; j++) { int i = tid + j * 256; if (i < 612) sIn[1 - cur][i] = pin[j]; }
#pragma unroll
            for (int j = 0; j < 2; j++) { int i = tid + j * 256; if (i < 288) sW[1 - cur][i] = pw[j]; }
        }
        __syncthreads();
    }

    int gyA = oy0 + oyr, gyB = gyA + 8, gx = ox0 + ox;
#pragma unroll
    for (int o = 0; o < 16; o++) {
        unsigned lo, hi;
        UNPACK2(lo, hi, accA[o]);
        g_f[((n * 32 + 2 * o) * 64 + gyA) * 64 + gx] = fmaxf(__uint_as_float(lo), 0.f);
        g_f[((n * 32 + 2 * o + 1) * 64 + gyA) * 64 + gx] = fmaxf(__uint_as_float(hi), 0.f);
        UNPACK2(lo, hi, accB[o]);
        g_f[((n * 32 + 2 * o) * 64 + gyB) * 64 + gx] = fmaxf(__uint_as_float(lo), 0.f);
        g_f[((n * 32 + 2 * o + 1) * 64 + gyB) * 64 + gx] = fmaxf(__uint_as_float(hi), 0.f);
    }
}

// =================== mp2: 32->2, k3, p1 (2 px/thread, 32x16 tile) ===================
__global__ void __launch_bounds__(256, 2)
mp2_kernel(const float* __restrict__ w, const float* __restrict__ b,
           float* __restrict__ out) {
    __shared__ __align__(8) float sIn[2][18 * 34];
    __shared__ __align__(8) float sW[2][18];
    int n = blockIdx.z;
    int ox0 = blockIdx.x * 32, oy0 = blockIdx.y * 16;
    int tid = threadIdx.x;
    int ox = tid & 31, oyr = tid >> 5;

    int iy0 = oy0 - 1, ix0 = ox0 - 1;

    float pin[3], pwv;
    {
        const float* src = &g_f[(n * 32 + 0) * 4096];
#pragma unroll
        for (int j = 0; j < 3; j++) {
            int i = tid + j * 256; float v = 0.f;
            if (i < 612) {
                int iy = i / 34, ix = i % 34;
                int gy = iy0 + iy, gx = ix0 + ix;
                if ((unsigned)gy < 64u && (unsigned)gx < 64u) v = src[gy * 64 + gx];
            }
            pin[j] = v;
        }
        pwv = (tid < 18) ? w[((tid & 1) * 32 + 0) * 9 + (tid >> 1)] : 0.f;
    }
#pragma unroll
    for (int j = 0; j < 3; j++) { int i = tid + j * 256; if (i < 612) sIn[0][i] = pin[j]; }
    if (tid < 18) sW[0][tid] = pwv;
    __syncthreads();

    unsigned long long accA2, accB2;
    PACK2(accA2, __float_as_uint(b[0]), __float_as_uint(b[1]));
    accB2 = accA2;

    for (int ic = 0; ic < 32; ic++) {
        int cur = ic & 1;
        if (ic < 31) {
            const float* src = &g_f[(n * 32 + ic + 1) * 4096];
#pragma unroll
            for (int j = 0; j < 3; j++) {
                int i = tid + j * 256; float v = 0.f;
                if (i < 612) {
                    int iy = i / 34, ix = i % 34;
                    int gy = iy0 + iy, gx = ix0 + ix;
                    if ((unsigned)gy < 64u && (unsigned)gx < 64u) v = src[gy * 64 + gx];
                }
                pin[j] = v;
            }
            pwv = (tid < 18) ? w[((tid & 1) * 32 + ic + 1) * 9 + (tid >> 1)] : 0.f;
        }
        const unsigned long long* wp2 = (const unsigned long long*)&sW[cur][0];
#pragma unroll
        for (int kh = 0; kh < 3; kh++) {
            const float* rA = &sIn[cur][(oyr + kh) * 34 + ox];
            const float* rB = rA + 8 * 34;
#pragma unroll
            for (int kw = 0; kw < 3; kw++) {
                unsigned long long w2 = wp2[kh * 3 + kw];
                FMA2(accA2, pack_dup(rA[kw]), w2);
                FMA2(accB2, pack_dup(rB[kw]), w2);
            }
        }
        if (ic < 31) {
#pragma unroll
            for (int j = 0; j < 3; j++) { int i = tid + j * 256; if (i < 612) sIn[1 - cur][i] = pin[j]; }
            if (tid < 18) sW[1 - cur][tid] = pwv;
        }
        __syncthreads();
    }
    int gyA = oy0 + oyr, gyB = gyA + 8, gx = ox0 + ox;
    unsigned lo, hi;
    UNPACK2(lo, hi, accA2);
    out[((n * 2 + 0) * 64 + gyA) * 64 + gx] = __uint_as_float(lo);
    out[((n * 2 + 1) * 64 + gyA) * 64 + gx] = __uint_as_float(hi);
    UNPACK2(lo, hi, accB2);
    out[((n * 2 + 0) * 64 + gyB) * 64 + gx] = __uint_as_float(lo);
    out[((n * 2 + 1) * 64 + gyB) * 64 + gx] = __uint_as_float(hi);
}

// =================== launch ===================
extern "C" void kernel_launch(void* const* d_in, const int* in_sizes, int n_in,
                              void* d_out, int out_size) {
    const float* images = (const float*)d_in[0];
    const float* actions = (const float*)d_in[1];
    const float* pe_w1 = (const float*)d_in[2];
    const float* pe_b1 = (const float*)d_in[3];
    const float* pe_w2 = (const float*)d_in[4];
    const float* pe_b2 = (const float*)d_in[5];
    const float* ae_w1 = (const float*)d_in[6];
    const float* ae_b1 = (const float*)d_in[7];
    const float* ae_w2 = (const float*)d_in[8];
    const float* ae_b2 = (const float*)d_in[9];
    const float* mp_w1 = (const float*)d_in[10];
    const float* mp_b1 = (const float*)d_in[11];
    const float* mp_w2 = (const float*)d_in[12];
    const float* mp_b2 = (const float*)d_in[13];
    float* out = (float*)d_out;

    ae_kernel<<<NB, 256>>>(actions, ae_w1, ae_b1, ae_w2, ae_b2);
    conv1_kernel<<<dim3(4, 8, NB), 256>>>(images, pe_w1, pe_b1);
    conv2_kernel<<<dim3(2, 4, NB), 256>>>(pe_w2, pe_b2);
    xconv_kernel<<<dim3(32, NB), 256>>>();
    mp1_kernel<<<dim3(2, 4, NB), 256>>>(mp_w1, mp_b1);
    mp2_kernel<<<dim3(2, 4, NB), 256>>>(mp_w2, mp_b2, out);
}